// round 6
// baseline (speedup 1.0000x reference)
#include <cuda_runtime.h>
#include <cuda_bf16.h>
#include <cuda_fp16.h>
#include <cstdint>

#define NN 100000
#define EE 1600000

// ---------------- scratch (device globals) -----------------------------------
__device__ int   g_deg[NN];
__device__ int   g_off[NN];
__device__ int   g_cur[NN];
__device__ float g_dinv[NN];
__device__ int   g_srcs[EE];
__device__ int   g_bsum[128];
__device__ int   g_flag;
__device__ __half g_ub[(size_t)NN * 128];   // u = A@Wl, fp16 (gather aggregand)
__device__ float  g_v [(size_t)NN * 128];   // v = A@Wr, fp32
__device__ float  g_h1[(size_t)NN * 128];
__device__ float  g_h [(size_t)NN * 128];
__device__ __align__(16) unsigned char g_w1hi[256 * 256];
__device__ __align__(16) unsigned char g_w1lo[256 * 256];
__device__ __align__(16) unsigned char g_w2hi[256 * 256];
__device__ __align__(16) unsigned char g_w2lo[256 * 256];
__device__ __align__(16) unsigned char g_wfhi[64 * 256];
__device__ __align__(16) unsigned char g_wflo[64 * 256];

// ---------------- side stream for CSR || GEMM1 overlap ------------------------
// Host-side resources only (no device memory). Created once, pre-main.
struct SideRes {
    cudaStream_t s;
    cudaEvent_t ea, eb;
    SideRes() {
        cudaStreamCreateWithFlags(&s, cudaStreamNonBlocking);
        cudaEventCreateWithFlags(&ea, cudaEventDisableTiming);
        cudaEventCreateWithFlags(&eb, cudaEventDisableTiming);
    }
};
static SideRes g_res;

// ---------------- helpers -----------------------------------------------------
__device__ __forceinline__ uint32_t smem_u32(const void* p) {
    uint32_t a;
    asm("{ .reg .u64 t; cvta.to.shared.u64 t, %1; cvt.u32.u64 %0, t; }" : "=r"(a) : "l"(p));
    return a;
}
__device__ __forceinline__ uint32_t swz(int row, int col) {
    uint32_t off = (uint32_t)row * 256u + (uint32_t)col * 2u;
    return off ^ (((uint32_t)row & 7u) << 4);
}
__device__ __forceinline__ void ldsm_x4(uint32_t* r, uint32_t addr) {
    asm volatile("ldmatrix.sync.aligned.m8n8.x4.shared.b16 {%0,%1,%2,%3}, [%4];"
                 : "=r"(r[0]), "=r"(r[1]), "=r"(r[2]), "=r"(r[3]) : "r"(addr));
}
__device__ __forceinline__ void mma_bf16(float* c, const uint32_t* a, const uint32_t* b) {
    asm volatile("mma.sync.aligned.m16n8k16.row.col.f32.bf16.bf16.f32 "
                 "{%0,%1,%2,%3}, {%4,%5,%6,%7}, {%8,%9}, {%0,%1,%2,%3};"
                 : "+f"(c[0]), "+f"(c[1]), "+f"(c[2]), "+f"(c[3])
                 : "r"(a[0]), "r"(a[1]), "r"(a[2]), "r"(a[3]), "r"(b[0]), "r"(b[1]));
}

// ---------------- CSR build ---------------------------------------------------
__global__ void k_zero() {
    int i = blockIdx.x * blockDim.x + threadIdx.x;
    if (i < NN) g_deg[i] = 0;
    if (i == 0) g_flag = 0;
}
__global__ void k_detect(const unsigned int* __restrict__ w) {
    int i = blockIdx.x * blockDim.x + threadIdx.x;
    if (w[2 * i + 1] != 0u) g_flag = 1;
}
__device__ __forceinline__ int ld_edge(const void* ei, long long pos, int is64) {
    if (is64) return (int)((const long long*)ei)[pos];
    return ((const int*)ei)[pos];
}
__global__ void k_hist(const void* __restrict__ ei) {
    int e = blockIdx.x * blockDim.x + threadIdx.x;
    if (e >= EE) return;
    int is64 = (g_flag == 0);
    atomicAdd(&g_deg[ld_edge(ei, (long long)EE + e, is64)], 1);
}
__global__ void k_scan1() {
    __shared__ int sh[1024];
    int i = blockIdx.x * 1024 + threadIdx.x;
    int v = (i < NN) ? g_deg[i] : 0;
    sh[threadIdx.x] = v;
    __syncthreads();
    for (int d = 1; d < 1024; d <<= 1) {
        int t = (threadIdx.x >= d) ? sh[threadIdx.x - d] : 0;
        __syncthreads();
        sh[threadIdx.x] += t;
        __syncthreads();
    }
    if (i < NN) g_off[i] = sh[threadIdx.x] - v;
    if (threadIdx.x == 1023) g_bsum[blockIdx.x] = sh[1023];
}
__global__ void k_scan2() {
    __shared__ int sh[128];
    int i = threadIdx.x;
    const int NB = (NN + 1023) / 1024;
    int v = (i < NB) ? g_bsum[i] : 0;
    sh[i] = v;
    __syncthreads();
    for (int d = 1; d < 128; d <<= 1) {
        int t = (i >= d) ? sh[i - d] : 0;
        __syncthreads();
        sh[i] += t;
        __syncthreads();
    }
    if (i < NB) g_bsum[i] = sh[i] - v;
}
__global__ void k_scan3() {
    int i = blockIdx.x * 1024 + threadIdx.x;
    if (i >= NN) return;
    int o = g_off[i] + g_bsum[i >> 10];
    g_off[i] = o;
    g_cur[i] = o;
    int d = g_deg[i];
    g_dinv[i] = 1.0f / (float)(d > 1 ? d : 1);
}
__global__ void k_scatter(const void* __restrict__ ei) {
    int e = blockIdx.x * blockDim.x + threadIdx.x;
    if (e >= EE) return;
    int is64 = (g_flag == 0);
    int s = ld_edge(ei, (long long)e, is64);
    int d = ld_edge(ei, (long long)EE + e, is64);
    g_srcs[atomicAdd(&g_cur[d], 1)] = s;
}

// ---------------- weight prep -------------------------------------------------
__global__ void k_prep_w(const float* __restrict__ W1l, const float* __restrict__ W1r,
                         const float* __restrict__ W2l, const float* __restrict__ W2r,
                         const float* __restrict__ Wlin) {
    int i = blockIdx.x * blockDim.x + threadIdx.x;
    float v;
    unsigned char *hi, *lo;
    uint32_t off;
    if (i < 65536) {
        int layer = i >> 15, e = i & 32767;
        int n = e >> 7, k = e & 127;
        const float* Wl = layer ? W2l : W1l;
        const float* Wr = layer ? W2r : W1r;
        v = (n < 128) ? Wl[k * 128 + n] : Wr[k * 128 + (n - 128)];
        hi = layer ? g_w2hi : g_w1hi;
        lo = layer ? g_w2lo : g_w1lo;
        off = swz(n, k);
    } else if (i < 65536 + 8192) {
        int e = i - 65536;
        int n = e >> 7, k = e & 127;
        v = Wlin[k * 64 + n];
        hi = g_wfhi; lo = g_wflo;
        off = swz(n, k);
    } else return;
    __nv_bfloat16 h = __float2bfloat16_rn(v);
    __nv_bfloat16 l = __float2bfloat16_rn(v - __bfloat162float(h));
    *(__nv_bfloat16*)(hi + off) = h;
    *(__nv_bfloat16*)(lo + off) = l;
}

// ---------------- mma.sync GEMM ----------------------------------------------
template <int NC, bool SPLIT>
__global__ void __launch_bounds__(256, 1) k_gemm_mma(
    const float* __restrict__ A,
    const unsigned char* __restrict__ Bhi, const unsigned char* __restrict__ Blo,
    const float* __restrict__ bias,
    float* __restrict__ C, __half* __restrict__ UB, float* __restrict__ V) {
    extern __shared__ unsigned char sm[];
    const int BIAS = 0;
    const int AHI = 1024;
    const int ALO = AHI + 32768;
    const int BHI = ALO + 32768;
    const int BLO = BHI + NC * 256;
    uint32_t sb = smem_u32(sm);
    int tid = threadIdx.x, wid = tid >> 5, lane = tid & 31;

    const int BW = NC * 256 / 16;
    for (int i = tid; i < BW; i += 256) {
        ((float4*)(sm + BHI))[i] = ((const float4*)Bhi)[i];
        ((float4*)(sm + BLO))[i] = ((const float4*)Blo)[i];
    }
    if (bias) for (int i = tid; i < NC; i += 256) ((float*)(sm + BIAS))[i] = bias[i];

    int row0 = blockIdx.x * 128;
    {
        int r = tid >> 1, half = tid & 1;
        int row = row0 + r;
        const float* ap = A + (size_t)row * 128 + half * 64;
        for (int cc = 0; cc < 64; cc += 4) {
            float4 v = (row < NN) ? *(const float4*)(ap + cc)
                                  : make_float4(0.f, 0.f, 0.f, 0.f);
            __nv_bfloat16 hx = __float2bfloat16_rn(v.x), hy = __float2bfloat16_rn(v.y);
            __nv_bfloat16 hz = __float2bfloat16_rn(v.z), hw = __float2bfloat16_rn(v.w);
            __nv_bfloat162 h0, h1, l0, l1;
            h0.x = hx; h0.y = hy; h1.x = hz; h1.y = hw;
            l0.x = __float2bfloat16_rn(v.x - __bfloat162float(hx));
            l0.y = __float2bfloat16_rn(v.y - __bfloat162float(hy));
            l1.x = __float2bfloat16_rn(v.z - __bfloat162float(hz));
            l1.y = __float2bfloat16_rn(v.w - __bfloat162float(hw));
            uint32_t so = swz(r, half * 64 + cc);
            *(__nv_bfloat162*)(sm + AHI + so)     = h0;
            *(__nv_bfloat162*)(sm + AHI + so + 4) = h1;
            *(__nv_bfloat162*)(sm + ALO + so)     = l0;
            *(__nv_bfloat162*)(sm + ALO + so + 4) = l1;
        }
    }
    __syncthreads();

    const int WARP_N = NC / 2;
    const int NPAIRS = WARP_N / 16;
    const int NB8    = WARP_N / 8;
    int warp_m = (wid & 3) * 32;
    int warp_n = (wid >> 2) * WARP_N;

    float c[2][NB8][4];
#pragma unroll
    for (int mb = 0; mb < 2; mb++)
#pragma unroll
        for (int nb = 0; nb < NB8; nb++)
#pragma unroll
            for (int j = 0; j < 4; j++) c[mb][nb][j] = 0.f;

    int a_r = ((lane >> 3) & 1) * 8 + (lane & 7);
    int a_c = (lane >> 4) * 8;
    int b_r = (lane >> 4) * 8 + (lane & 7);
    int b_c = ((lane >> 3) & 1) * 8;

#pragma unroll
    for (int pass = 0; pass < 3; pass++) {
        uint32_t abase = sb + (pass == 2 ? ALO : AHI);
        uint32_t bbase = sb + (pass == 1 ? BLO : BHI);
#pragma unroll
        for (int k = 0; k < 128; k += 16) {
            uint32_t afr[2][4];
#pragma unroll
            for (int mb = 0; mb < 2; mb++)
                ldsm_x4(afr[mb], abase + swz(warp_m + mb * 16 + a_r, k + a_c));
#pragma unroll
            for (int np = 0; np < NPAIRS; np++) {
                uint32_t bfr[4];
                ldsm_x4(bfr, bbase + swz(warp_n + np * 16 + b_r, k + b_c));
#pragma unroll
                for (int mb = 0; mb < 2; mb++) {
                    mma_bf16(c[mb][np * 2],     afr[mb], bfr);
                    mma_bf16(c[mb][np * 2 + 1], afr[mb], bfr + 2);
                }
            }
        }
    }

    int g = lane >> 2, tg = lane & 3;
    if (SPLIT) {
        bool is_u = (warp_n < 128);
#pragma unroll
        for (int mb = 0; mb < 2; mb++) {
#pragma unroll
            for (int nb = 0; nb < NB8; nb++) {
                int col = warp_n + nb * 8 + tg * 2;
                int r1 = row0 + warp_m + mb * 16 + g;
                int r2 = r1 + 8;
                if (is_u) {
                    if (r1 < NN)
                        *(__half2*)(UB + (size_t)r1 * 128 + col) =
                            __floats2half2_rn(c[mb][nb][0], c[mb][nb][1]);
                    if (r2 < NN)
                        *(__half2*)(UB + (size_t)r2 * 128 + col) =
                            __floats2half2_rn(c[mb][nb][2], c[mb][nb][3]);
                } else {
                    int cv = col - 128;
                    if (r1 < NN)
                        *(float2*)(V + (size_t)r1 * 128 + cv) =
                            make_float2(c[mb][nb][0], c[mb][nb][1]);
                    if (r2 < NN)
                        *(float2*)(V + (size_t)r2 * 128 + cv) =
                            make_float2(c[mb][nb][2], c[mb][nb][3]);
                }
            }
        }
    } else {
        const float* bs = (const float*)(sm + BIAS);
#pragma unroll
        for (int mb = 0; mb < 2; mb++) {
#pragma unroll
            for (int nb = 0; nb < NB8; nb++) {
                int col = warp_n + nb * 8 + tg * 2;
                float bx = bs[col], by = bs[col + 1];
                int r1 = row0 + warp_m + mb * 16 + g;
                if (r1 < NN)
                    *(float2*)(C + (size_t)r1 * NC + col) =
                        make_float2(c[mb][nb][0] + bx, c[mb][nb][1] + by);
                int r2 = r1 + 8;
                if (r2 < NN)
                    *(float2*)(C + (size_t)r2 * NC + col) =
                        make_float2(c[mb][nb][2] + bx, c[mb][nb][3] + by);
            }
        }
    }
}

// ---------------- aggregation: fp16 gather, 8-deep MLP, fp32 accumulate ------
__global__ void __launch_bounds__(256) k_agg(
    const __half* __restrict__ ub,
    const float* __restrict__ v,
    const float* __restrict__ bias,
    const float* __restrict__ res,
    float* __restrict__ out) {
    int node = blockIdx.x * 8 + (threadIdx.x >> 5);
    if (node >= NN) return;
    int lane = threadIdx.x & 31;
    int off = g_off[node];
    int d = g_deg[node];

    float ax = 0.f, ay = 0.f, az = 0.f, aw = 0.f;
    float bx_ = 0.f, by_ = 0.f, bz_ = 0.f, bw_ = 0.f;
    const __half* uvb = ub + (size_t)lane * 4;

    int e = 0;
#pragma unroll 1
    for (; e + 8 <= d; e += 8) {
        int s0 = __ldg(&g_srcs[off + e]);
        int s1 = __ldg(&g_srcs[off + e + 1]);
        int s2 = __ldg(&g_srcs[off + e + 2]);
        int s3 = __ldg(&g_srcs[off + e + 3]);
        int s4 = __ldg(&g_srcs[off + e + 4]);
        int s5 = __ldg(&g_srcs[off + e + 5]);
        int s6 = __ldg(&g_srcs[off + e + 6]);
        int s7 = __ldg(&g_srcs[off + e + 7]);
        uint2 r0 = *(const uint2*)(uvb + (size_t)s0 * 128);
        uint2 r1 = *(const uint2*)(uvb + (size_t)s1 * 128);
        uint2 r2 = *(const uint2*)(uvb + (size_t)s2 * 128);
        uint2 r3 = *(const uint2*)(uvb + (size_t)s3 * 128);
        uint2 r4 = *(const uint2*)(uvb + (size_t)s4 * 128);
        uint2 r5 = *(const uint2*)(uvb + (size_t)s5 * 128);
        uint2 r6 = *(const uint2*)(uvb + (size_t)s6 * 128);
        uint2 r7 = *(const uint2*)(uvb + (size_t)s7 * 128);
        float2 a0 = __half22float2(*(__half2*)&r0.x), c0 = __half22float2(*(__half2*)&r0.y);
        float2 a1 = __half22float2(*(__half2*)&r1.x), c1 = __half22float2(*(__half2*)&r1.y);
        float2 a2 = __half22float2(*(__half2*)&r2.x), c2 = __half22float2(*(__half2*)&r2.y);
        float2 a3 = __half22float2(*(__half2*)&r3.x), c3 = __half22float2(*(__half2*)&r3.y);
        float2 a4 = __half22float2(*(__half2*)&r4.x), c4 = __half22float2(*(__half2*)&r4.y);
        float2 a5 = __half22float2(*(__half2*)&r5.x), c5 = __half22float2(*(__half2*)&r5.y);
        float2 a6 = __half22float2(*(__half2*)&r6.x), c6 = __half22float2(*(__half2*)&r6.y);
        float2 a7 = __half22float2(*(__half2*)&r7.x), c7 = __half22float2(*(__half2*)&r7.y);
        ax += a0.x + a1.x + a2.x + a3.x;  bx_ += a4.x + a5.x + a6.x + a7.x;
        ay += a0.y + a1.y + a2.y + a3.y;  by_ += a4.y + a5.y + a6.y + a7.y;
        az += c0.x + c1.x + c2.x + c3.x;  bz_ += c4.x + c5.x + c6.x + c7.x;
        aw += c0.y + c1.y + c2.y + c3.y;  bw_ += c4.y + c5.y + c6.y + c7.y;
    }
    for (; e < d; e++) {
        int s = __ldg(&g_srcs[off + e]);
        uint2 r = *(const uint2*)(uvb + (size_t)s * 128);
        float2 a = __half22float2(*(__half2*)&r.x), c = __half22float2(*(__half2*)&r.y);
        ax += a.x; ay += a.y; az += c.x; aw += c.y;
    }
    ax += bx_; ay += by_; az += bz_; aw += bw_;

    float di = g_dinv[node];
    float4 vv = *(const float4*)(v + (size_t)node * 128 + lane * 4);
    float4 b = *(const float4*)(bias + lane * 4);
    float rx = fmaf(ax, di, vv.x + b.x);
    float ry = fmaf(ay, di, vv.y + b.y);
    float rz = fmaf(az, di, vv.z + b.z);
    float rw = fmaf(aw, di, vv.w + b.w);
    if (res) {
        float4 h = *(const float4*)(res + (size_t)node * 128 + lane * 4);
        rx += h.x; ry += h.y; rz += h.z; rw += h.w;
    }
    rx = fmaxf(rx, 0.f); ry = fmaxf(ry, 0.f);
    rz = fmaxf(rz, 0.f); rw = fmaxf(rw, 0.f);
    *(float4*)(out + (size_t)node * 128 + lane * 4) = make_float4(rx, ry, rz, rw);
}

// ---------------- launch ------------------------------------------------------
extern "C" void kernel_launch(void* const* d_in, const int* in_sizes, int n_in,
                              void* d_out, int out_size) {
    const float* x    = (const float*)d_in[0];
    const void*  ei   = d_in[1];
    const float* W1l  = (const float*)d_in[2];
    const float* b1   = (const float*)d_in[3];
    const float* W1r  = (const float*)d_in[4];
    const float* W2l  = (const float*)d_in[5];
    const float* b2   = (const float*)d_in[6];
    const float* W2r  = (const float*)d_in[7];
    const float* Wlin = (const float*)d_in[8];
    const float* blin = (const float*)d_in[9];
    float* out = (float*)d_out;

    const size_t SM_DUAL  = 1024 + 2 * 32768 + 2 * 256 * 256;
    const size_t SM_FINAL = 1024 + 2 * 32768 + 2 * 64 * 256;
    cudaFuncSetAttribute(k_gemm_mma<256, true>, cudaFuncAttributeMaxDynamicSharedMemorySize, (int)SM_DUAL);
    cudaFuncSetAttribute(k_gemm_mma<64, false>, cudaFuncAttributeMaxDynamicSharedMemorySize, (int)SM_FINAL);

    void *p_ub, *p_v, *p_h1, *p_h, *p_w1h, *p_w1l, *p_w2h, *p_w2l, *p_wfh, *p_wfl;
    cudaGetSymbolAddress(&p_ub, g_ub);
    cudaGetSymbolAddress(&p_v,  g_v);
    cudaGetSymbolAddress(&p_h1, g_h1);
    cudaGetSymbolAddress(&p_h,  g_h);
    cudaGetSymbolAddress(&p_w1h, g_w1hi);
    cudaGetSymbolAddress(&p_w1l, g_w1lo);
    cudaGetSymbolAddress(&p_w2h, g_w2hi);
    cudaGetSymbolAddress(&p_w2l, g_w2lo);
    cudaGetSymbolAddress(&p_wfh, g_wfhi);
    cudaGetSymbolAddress(&p_wfl, g_wflo);
    __half* ub = (__half*)p_ub;
    float*  vv = (float*)p_v;
    float*  h1 = (float*)p_h1;
    float*  h  = (float*)p_h;

    const int NB_N   = (NN + 255) / 256;
    const int NB_E   = (EE + 255) / 256;
    const int NB_SC  = (NN + 1023) / 1024;
    const int NB_TC  = (NN + 127) / 128;
    const int NB_AGG = (NN + 7) / 8;

    // Fork: CSR build on side stream, concurrent with weight prep + GEMM1.
    cudaEventRecord(g_res.ea, 0);
    cudaStreamWaitEvent(g_res.s, g_res.ea, 0);
    k_zero<<<NB_N, 256, 0, g_res.s>>>();
    k_detect<<<16, 256, 0, g_res.s>>>((const unsigned int*)ei);
    k_hist<<<NB_E, 256, 0, g_res.s>>>(ei);
    k_scan1<<<NB_SC, 1024, 0, g_res.s>>>();
    k_scan2<<<1, 128, 0, g_res.s>>>();
    k_scan3<<<NB_SC, 1024, 0, g_res.s>>>();
    k_scatter<<<NB_E, 256, 0, g_res.s>>>(ei);
    cudaEventRecord(g_res.eb, g_res.s);

    // Main stream: weight prep + layer-1 GEMM (independent of CSR)
    k_prep_w<<<(73728 + 255) / 256, 256>>>(W1l, W1r, W2l, W2r, Wlin);
    k_gemm_mma<256, true><<<NB_TC, 256, SM_DUAL>>>(x, (unsigned char*)p_w1h, (unsigned char*)p_w1l, nullptr, nullptr, ub, vv);

    // Join: aggregation needs the CSR
    cudaStreamWaitEvent(0, g_res.eb, 0);
    k_agg<<<NB_AGG, 256>>>(ub, vv, b1, nullptr, h1);
    k_gemm_mma<256, true><<<NB_TC, 256, SM_DUAL>>>(h1, (unsigned char*)p_w2h, (unsigned char*)p_w2l, nullptr, nullptr, ub, vv);
    k_agg<<<NB_AGG, 256>>>(ub, vv, b2, h1, h);
    k_gemm_mma<64, false><<<NB_TC, 256, SM_FINAL>>>(h, (unsigned char*)p_wfh, (unsigned char*)p_wfl, blin, out, nullptr, nullptr);
}

// round 9
// speedup vs baseline: 1.3305x; 1.3305x over previous
#include <cuda_runtime.h>
#include <cuda_bf16.h>
#include <cuda_fp16.h>
#include <cstdint>

#define NN 100000
#define EE 1600000

// ---------------- scratch (device globals) -----------------------------------
__device__ int   g_deg[NN];
__device__ int   g_off[NN];
__device__ int   g_cur[NN];
__device__ float g_dinv[NN];
__device__ int   g_srcs[EE];
__device__ int   g_bsum[128];
__device__ int   g_flag;
__device__ __align__(16) __half g_ub[(size_t)NN * 128];   // u = A@Wl, fp16
__device__ float  g_v [(size_t)NN * 128];                 // v = A@Wr, fp32
__device__ float  g_h1[(size_t)NN * 128];
__device__ float  g_h [(size_t)NN * 128];
__device__ __align__(16) unsigned char g_w1hi[256 * 256];
__device__ __align__(16) unsigned char g_w1lo[256 * 256];
__device__ __align__(16) unsigned char g_w2hi[256 * 256];
__device__ __align__(16) unsigned char g_w2lo[256 * 256];
__device__ __align__(16) unsigned char g_wfhi[64 * 256];
__device__ __align__(16) unsigned char g_wflo[64 * 256];

// ---------------- helpers -----------------------------------------------------
__device__ __forceinline__ uint32_t smem_u32(const void* p) {
    uint32_t a;
    asm("{ .reg .u64 t; cvta.to.shared.u64 t, %1; cvt.u32.u64 %0, t; }" : "=r"(a) : "l"(p));
    return a;
}
__device__ __forceinline__ uint32_t swz(int row, int col) {
    uint32_t off = (uint32_t)row * 256u + (uint32_t)col * 2u;
    return off ^ (((uint32_t)row & 7u) << 4);
}
__device__ __forceinline__ void ldsm_x4(uint32_t* r, uint32_t addr) {
    asm volatile("ldmatrix.sync.aligned.m8n8.x4.shared.b16 {%0,%1,%2,%3}, [%4];"
                 : "=r"(r[0]), "=r"(r[1]), "=r"(r[2]), "=r"(r[3]) : "r"(addr));
}
__device__ __forceinline__ void mma_bf16(float* c, const uint32_t* a, const uint32_t* b) {
    asm volatile("mma.sync.aligned.m16n8k16.row.col.f32.bf16.bf16.f32 "
                 "{%0,%1,%2,%3}, {%4,%5,%6,%7}, {%8,%9}, {%0,%1,%2,%3};"
                 : "+f"(c[0]), "+f"(c[1]), "+f"(c[2]), "+f"(c[3])
                 : "r"(a[0]), "r"(a[1]), "r"(a[2]), "r"(a[3]), "r"(b[0]), "r"(b[1]));
}

// ---------------- CSR build ---------------------------------------------------
// zero degrees + detect int32-vs-int64 edge layout (g_flag monotonic; module-load 0)
__global__ void k_init(const unsigned int* __restrict__ w) {
    int i = blockIdx.x * blockDim.x + threadIdx.x;
    if (i < NN) g_deg[i] = 0;
    if (i < 4096 && w[2 * i + 1] != 0u) g_flag = 1;
}
__device__ __forceinline__ int ld_edge(const void* ei, long long pos, int is64) {
    if (is64) return (int)((const long long*)ei)[pos];
    return ((const int*)ei)[pos];
}
__global__ void k_hist(const void* __restrict__ ei) {
    int e = blockIdx.x * blockDim.x + threadIdx.x;
    if (e >= EE) return;
    int is64 = (g_flag == 0);
    atomicAdd(&g_deg[ld_edge(ei, (long long)EE + e, is64)], 1);
}
__global__ void k_scan1() {
    __shared__ int sh[1024];
    int i = blockIdx.x * 1024 + threadIdx.x;
    int v = (i < NN) ? g_deg[i] : 0;
    sh[threadIdx.x] = v;
    __syncthreads();
    for (int d = 1; d < 1024; d <<= 1) {
        int t = (threadIdx.x >= d) ? sh[threadIdx.x - d] : 0;
        __syncthreads();
        sh[threadIdx.x] += t;
        __syncthreads();
    }
    if (i < NN) g_off[i] = sh[threadIdx.x] - v;      // exclusive within block
    if (threadIdx.x == 1023) g_bsum[blockIdx.x] = sh[1023];  // block total
}
// scan3 also folds the cross-block prefix (warp 0 sums bsum[0..b-1])
__global__ void k_scan3() {
    __shared__ int sbase;
    if (threadIdx.x < 32) {
        int v = 0;
        for (int j = (int)threadIdx.x; j < (int)blockIdx.x; j += 32) v += g_bsum[j];
        for (int o = 16; o; o >>= 1) v += __shfl_xor_sync(0xFFFFFFFFu, v, o);
        if (threadIdx.x == 0) sbase = v;
    }
    __syncthreads();
    int i = blockIdx.x * 1024 + threadIdx.x;
    if (i >= NN) return;
    int o = g_off[i] + sbase;
    g_off[i] = o;
    g_cur[i] = o;
    int d = g_deg[i];
    g_dinv[i] = 1.0f / (float)(d > 1 ? d : 1);
}
__global__ void k_scatter(const void* __restrict__ ei) {
    int e = blockIdx.x * blockDim.x + threadIdx.x;
    if (e >= EE) return;
    int is64 = (g_flag == 0);
    int s = ld_edge(ei, (long long)e, is64);
    int d = ld_edge(ei, (long long)EE + e, is64);
    g_srcs[atomicAdd(&g_cur[d], 1)] = s;
}

// ---------------- weight prep -------------------------------------------------
__global__ void k_prep_w(const float* __restrict__ W1l, const float* __restrict__ W1r,
                         const float* __restrict__ W2l, const float* __restrict__ W2r,
                         const float* __restrict__ Wlin) {
    int i = blockIdx.x * blockDim.x + threadIdx.x;
    float v;
    unsigned char *hi, *lo;
    uint32_t off;
    if (i < 65536) {
        int layer = i >> 15, e = i & 32767;
        int n = e >> 7, k = e & 127;
        const float* Wl = layer ? W2l : W1l;
        const float* Wr = layer ? W2r : W1r;
        v = (n < 128) ? Wl[k * 128 + n] : Wr[k * 128 + (n - 128)];
        hi = layer ? g_w2hi : g_w1hi;
        lo = layer ? g_w2lo : g_w1lo;
        off = swz(n, k);
    } else if (i < 65536 + 8192) {
        int e = i - 65536;
        int n = e >> 7, k = e & 127;
        v = Wlin[k * 64 + n];
        hi = g_wfhi; lo = g_wflo;
        off = swz(n, k);
    } else return;
    __nv_bfloat16 h = __float2bfloat16_rn(v);
    __nv_bfloat16 l = __float2bfloat16_rn(v - __bfloat162float(h));
    *(__nv_bfloat16*)(hi + off) = h;
    *(__nv_bfloat16*)(lo + off) = l;
}

// ---------------- mma.sync GEMM ----------------------------------------------
template <int NC, bool SPLIT>
__global__ void __launch_bounds__(256, 1) k_gemm_mma(
    const float* __restrict__ A,
    const unsigned char* __restrict__ Bhi, const unsigned char* __restrict__ Blo,
    const float* __restrict__ bias,
    float* __restrict__ C, __half* __restrict__ UB, float* __restrict__ V) {
    extern __shared__ unsigned char sm[];
    const int BIAS = 0;
    const int AHI = 1024;
    const int ALO = AHI + 32768;
    const int BHI = ALO + 32768;
    const int BLO = BHI + NC * 256;
    uint32_t sb = smem_u32(sm);
    int tid = threadIdx.x, wid = tid >> 5, lane = tid & 31;

    const int BW = NC * 256 / 16;
    for (int i = tid; i < BW; i += 256) {
        ((float4*)(sm + BHI))[i] = ((const float4*)Bhi)[i];
        ((float4*)(sm + BLO))[i] = ((const float4*)Blo)[i];
    }
    if (bias) for (int i = tid; i < NC; i += 256) ((float*)(sm + BIAS))[i] = bias[i];

    int row0 = blockIdx.x * 128;
    {
        int r = tid >> 1, half = tid & 1;
        int row = row0 + r;
        const float* ap = A + (size_t)row * 128 + half * 64;
        for (int cc = 0; cc < 64; cc += 4) {
            float4 v = (row < NN) ? *(const float4*)(ap + cc)
                                  : make_float4(0.f, 0.f, 0.f, 0.f);
            __nv_bfloat16 hx = __float2bfloat16_rn(v.x), hy = __float2bfloat16_rn(v.y);
            __nv_bfloat16 hz = __float2bfloat16_rn(v.z), hw = __float2bfloat16_rn(v.w);
            __nv_bfloat162 h0, h1, l0, l1;
            h0.x = hx; h0.y = hy; h1.x = hz; h1.y = hw;
            l0.x = __float2bfloat16_rn(v.x - __bfloat162float(hx));
            l0.y = __float2bfloat16_rn(v.y - __bfloat162float(hy));
            l1.x = __float2bfloat16_rn(v.z - __bfloat162float(hz));
            l1.y = __float2bfloat16_rn(v.w - __bfloat162float(hw));
            uint32_t so = swz(r, half * 64 + cc);
            *(__nv_bfloat162*)(sm + AHI + so)     = h0;
            *(__nv_bfloat162*)(sm + AHI + so + 4) = h1;
            *(__nv_bfloat162*)(sm + ALO + so)     = l0;
            *(__nv_bfloat162*)(sm + ALO + so + 4) = l1;
        }
    }
    __syncthreads();

    const int WARP_N = NC / 2;
    const int NPAIRS = WARP_N / 16;
    const int NB8    = WARP_N / 8;
    int warp_m = (wid & 3) * 32;
    int warp_n = (wid >> 2) * WARP_N;

    float c[2][NB8][4];
#pragma unroll
    for (int mb = 0; mb < 2; mb++)
#pragma unroll
        for (int nb = 0; nb < NB8; nb++)
#pragma unroll
            for (int j = 0; j < 4; j++) c[mb][nb][j] = 0.f;

    int a_r = ((lane >> 3) & 1) * 8 + (lane & 7);
    int a_c = (lane >> 4) * 8;
    int b_r = (lane >> 4) * 8 + (lane & 7);
    int b_c = ((lane >> 3) & 1) * 8;

#pragma unroll
    for (int pass = 0; pass < 3; pass++) {
        uint32_t abase = sb + (pass == 2 ? ALO : AHI);
        uint32_t bbase = sb + (pass == 1 ? BLO : BHI);
#pragma unroll
        for (int k = 0; k < 128; k += 16) {
            uint32_t afr[2][4];
#pragma unroll
            for (int mb = 0; mb < 2; mb++)
                ldsm_x4(afr[mb], abase + swz(warp_m + mb * 16 + a_r, k + a_c));
#pragma unroll
            for (int np = 0; np < NPAIRS; np++) {
                uint32_t bfr[4];
                ldsm_x4(bfr, bbase + swz(warp_n + np * 16 + b_r, k + b_c));
#pragma unroll
                for (int mb = 0; mb < 2; mb++) {
                    mma_bf16(c[mb][np * 2],     afr[mb], bfr);
                    mma_bf16(c[mb][np * 2 + 1], afr[mb], bfr + 2);
                }
            }
        }
    }

    int g = lane >> 2, tg = lane & 3;
    if (SPLIT) {
        bool is_u = (warp_n < 128);
#pragma unroll
        for (int mb = 0; mb < 2; mb++) {
#pragma unroll
            for (int nb = 0; nb < NB8; nb++) {
                int col = warp_n + nb * 8 + tg * 2;
                int r1 = row0 + warp_m + mb * 16 + g;
                int r2 = r1 + 8;
                if (is_u) {
                    if (r1 < NN)
                        *(__half2*)(UB + (size_t)r1 * 128 + col) =
                            __floats2half2_rn(c[mb][nb][0], c[mb][nb][1]);
                    if (r2 < NN)
                        *(__half2*)(UB + (size_t)r2 * 128 + col) =
                            __floats2half2_rn(c[mb][nb][2], c[mb][nb][3]);
                } else {
                    int cv = col - 128;
                    if (r1 < NN)
                        *(float2*)(V + (size_t)r1 * 128 + cv) =
                            make_float2(c[mb][nb][0], c[mb][nb][1]);
                    if (r2 < NN)
                        *(float2*)(V + (size_t)r2 * 128 + cv) =
                            make_float2(c[mb][nb][2], c[mb][nb][3]);
                }
            }
        }
    } else {
        const float* bs = (const float*)(sm + BIAS);
#pragma unroll
        for (int mb = 0; mb < 2; mb++) {
#pragma unroll
            for (int nb = 0; nb < NB8; nb++) {
                int col = warp_n + nb * 8 + tg * 2;
                float bx = bs[col], by = bs[col + 1];
                int r1 = row0 + warp_m + mb * 16 + g;
                if (r1 < NN)
                    *(float2*)(C + (size_t)r1 * NC + col) =
                        make_float2(c[mb][nb][0] + bx, c[mb][nb][1] + by);
                int r2 = r1 + 8;
                if (r2 < NN)
                    *(float2*)(C + (size_t)r2 * NC + col) =
                        make_float2(c[mb][nb][2] + bx, c[mb][nb][3] + by);
            }
        }
    }
}

// ---------------- aggregation: 2 edges/warp-iter, 16B/lane, shfl fold --------
// lanes 0-15: edge e, lanes 16-31: edge e+1. Lane covers 8 halves (16B).
__global__ void __launch_bounds__(256) k_agg(
    const __half* __restrict__ ub,
    const float* __restrict__ v,
    const float* __restrict__ bias,
    const float* __restrict__ res,
    float* __restrict__ out) {
    int node = blockIdx.x * 8 + (threadIdx.x >> 5);
    if (node >= NN) return;
    int lane = threadIdx.x & 31;
    int hf = lane & 15;       // feature group
    int side = lane >> 4;     // edge parity
    int off = g_off[node];
    int d = g_deg[node];

    float a[8];
#pragma unroll
    for (int j = 0; j < 8; j++) a[j] = 0.f;
    const __half* ubf = ub + hf * 8;

    int e = 0;
#pragma unroll 1
    for (; e + 4 <= d; e += 4) {
        int sA = __ldg(&g_srcs[off + e + side]);
        int sB = __ldg(&g_srcs[off + e + 2 + side]);
        uint4 rA = *(const uint4*)(ubf + (size_t)sA * 128);
        uint4 rB = *(const uint4*)(ubf + (size_t)sB * 128);
        float2 p0 = __half22float2(*(__half2*)&rA.x), q0 = __half22float2(*(__half2*)&rB.x);
        float2 p1 = __half22float2(*(__half2*)&rA.y), q1 = __half22float2(*(__half2*)&rB.y);
        float2 p2 = __half22float2(*(__half2*)&rA.z), q2 = __half22float2(*(__half2*)&rB.z);
        float2 p3 = __half22float2(*(__half2*)&rA.w), q3 = __half22float2(*(__half2*)&rB.w);
        a[0] += p0.x + q0.x; a[1] += p0.y + q0.y;
        a[2] += p1.x + q1.x; a[3] += p1.y + q1.y;
        a[4] += p2.x + q2.x; a[5] += p2.y + q2.y;
        a[6] += p3.x + q3.x; a[7] += p3.y + q3.y;
    }
    for (; e < d; e += 2) {
        int idx = e + side;
        if (idx < d) {
            int s = __ldg(&g_srcs[off + idx]);
            uint4 r = *(const uint4*)(ubf + (size_t)s * 128);
            float2 p0 = __half22float2(*(__half2*)&r.x);
            float2 p1 = __half22float2(*(__half2*)&r.y);
            float2 p2 = __half22float2(*(__half2*)&r.z);
            float2 p3 = __half22float2(*(__half2*)&r.w);
            a[0] += p0.x; a[1] += p0.y; a[2] += p1.x; a[3] += p1.y;
            a[4] += p2.x; a[5] += p2.y; a[6] += p3.x; a[7] += p3.y;
        }
    }

    // fold the two edge-halves of the warp
#pragma unroll
    for (int j = 0; j < 8; j++) a[j] += __shfl_xor_sync(0xFFFFFFFFu, a[j], 16);

    if (side == 0) {
        float di = g_dinv[node];
        const float* vp = v + (size_t)node * 128 + hf * 8;
        const float* bp = bias + hf * 8;
        float4 v0 = *(const float4*)vp, v1 = *(const float4*)(vp + 4);
        float4 b0 = *(const float4*)bp, b1 = *(const float4*)(bp + 4);
        float o[8];
        o[0] = fmaf(a[0], di, v0.x + b0.x);
        o[1] = fmaf(a[1], di, v0.y + b0.y);
        o[2] = fmaf(a[2], di, v0.z + b0.z);
        o[3] = fmaf(a[3], di, v0.w + b0.w);
        o[4] = fmaf(a[4], di, v1.x + b1.x);
        o[5] = fmaf(a[5], di, v1.y + b1.y);
        o[6] = fmaf(a[6], di, v1.z + b1.z);
        o[7] = fmaf(a[7], di, v1.w + b1.w);
        if (res) {
            const float* rp = res + (size_t)node * 128 + hf * 8;
            float4 r0 = *(const float4*)rp, r1 = *(const float4*)(rp + 4);
            o[0] += r0.x; o[1] += r0.y; o[2] += r0.z; o[3] += r0.w;
            o[4] += r1.x; o[5] += r1.y; o[6] += r1.z; o[7] += r1.w;
        }
#pragma unroll
        for (int j = 0; j < 8; j++) o[j] = fmaxf(o[j], 0.f);
        float* op = out + (size_t)node * 128 + hf * 8;
        *(float4*)op       = make_float4(o[0], o[1], o[2], o[3]);
        *(float4*)(op + 4) = make_float4(o[4], o[5], o[6], o[7]);
    }
}

// ---------------- launch ------------------------------------------------------
extern "C" void kernel_launch(void* const* d_in, const int* in_sizes, int n_in,
                              void* d_out, int out_size) {
    const float* x    = (const float*)d_in[0];
    const void*  ei   = d_in[1];
    const float* W1l  = (const float*)d_in[2];
    const float* b1   = (const float*)d_in[3];
    const float* W1r  = (const float*)d_in[4];
    const float* W2l  = (const float*)d_in[5];
    const float* b2   = (const float*)d_in[6];
    const float* W2r  = (const float*)d_in[7];
    const float* Wlin = (const float*)d_in[8];
    const float* blin = (const float*)d_in[9];
    float* out = (float*)d_out;

    const size_t SM_DUAL  = 1024 + 2 * 32768 + 2 * 256 * 256;
    const size_t SM_FINAL = 1024 + 2 * 32768 + 2 * 64 * 256;
    cudaFuncSetAttribute(k_gemm_mma<256, true>, cudaFuncAttributeMaxDynamicSharedMemorySize, (int)SM_DUAL);
    cudaFuncSetAttribute(k_gemm_mma<64, false>, cudaFuncAttributeMaxDynamicSharedMemorySize, (int)SM_FINAL);

    void *p_ub, *p_v, *p_h1, *p_h, *p_w1h, *p_w1l, *p_w2h, *p_w2l, *p_wfh, *p_wfl;
    cudaGetSymbolAddress(&p_ub, g_ub);
    cudaGetSymbolAddress(&p_v,  g_v);
    cudaGetSymbolAddress(&p_h1, g_h1);
    cudaGetSymbolAddress(&p_h,  g_h);
    cudaGetSymbolAddress(&p_w1h, g_w1hi);
    cudaGetSymbolAddress(&p_w1l, g_w1lo);
    cudaGetSymbolAddress(&p_w2h, g_w2hi);
    cudaGetSymbolAddress(&p_w2l, g_w2lo);
    cudaGetSymbolAddress(&p_wfh, g_wfhi);
    cudaGetSymbolAddress(&p_wfl, g_wflo);
    __half* ub = (__half*)p_ub;
    float*  vv = (float*)p_v;
    float*  h1 = (float*)p_h1;
    float*  h  = (float*)p_h;

    const int NB_N   = (NN + 255) / 256;
    const int NB_E   = (EE + 255) / 256;
    const int NB_SC  = (NN + 1023) / 1024;
    const int NB_TC  = (NN + 127) / 128;
    const int NB_AGG = (NN + 7) / 8;

    k_init<<<NB_N, 256>>>((const unsigned int*)ei);
    k_prep_w<<<(73728 + 255) / 256, 256>>>(W1l, W1r, W2l, W2r, Wlin);
    k_hist<<<NB_E, 256>>>(ei);
    k_scan1<<<NB_SC, 1024>>>();
    k_scan3<<<NB_SC, 1024>>>();
    k_scatter<<<NB_E, 256>>>(ei);

    k_gemm_mma<256, true><<<NB_TC, 256, SM_DUAL>>>(x, (unsigned char*)p_w1h, (unsigned char*)p_w1l, nullptr, nullptr, ub, vv);
    k_agg<<<NB_AGG, 256>>>(ub, vv, b1, nullptr, h1);
    k_gemm_mma<256, true><<<NB_TC, 256, SM_DUAL>>>(h1, (unsigned char*)p_w2h, (unsigned char*)p_w2l, nullptr, nullptr, ub, vv);
    k_agg<<<NB_AGG, 256>>>(ub, vv, b2, h1, h);
    k_gemm_mma<64, false><<<NB_TC, 256, SM_FINAL>>>(h, (unsigned char*)p_wfh, (unsigned char*)p_wfl, blin, out, nullptr, nullptr);
}

// round 16
// speedup vs baseline: 1.4068x; 1.0574x over previous
#include <cuda_runtime.h>
#include <cuda_bf16.h>
#include <cuda_fp16.h>
#include <cstdint>

#define NN 100000
#define EE 1600000

// ---------------- scratch (device globals) -----------------------------------
__device__ int   g_deg[NN];
__device__ int   g_off[NN];
__device__ int   g_cur[NN];
__device__ float g_dinv[NN];
__device__ int   g_srcs[EE];
__device__ int   g_bsum[128];
__device__ int   g_flag;
__device__ __align__(16) __half g_ub[(size_t)NN * 128];   // u = A@Wl, fp16 (gather target)
__device__ __align__(16) __half g_v [(size_t)NN * 128];   // v = A@Wr, fp16 (streamed)
__device__ float  g_h1[(size_t)NN * 128];
__device__ float  g_h [(size_t)NN * 128];
__device__ __align__(16) unsigned char g_w1hi[256 * 256];
__device__ __align__(16) unsigned char g_w1lo[256 * 256];
__device__ __align__(16) unsigned char g_w2hi[256 * 256];
__device__ __align__(16) unsigned char g_w2lo[256 * 256];
__device__ __align__(16) unsigned char g_wfhi[64 * 256];
__device__ __align__(16) unsigned char g_wflo[64 * 256];

// ---------------- helpers -----------------------------------------------------
__device__ __forceinline__ uint32_t smem_u32(const void* p) {
    uint32_t a;
    asm("{ .reg .u64 t; cvta.to.shared.u64 t, %1; cvt.u32.u64 %0, t; }" : "=r"(a) : "l"(p));
    return a;
}
__device__ __forceinline__ uint32_t swz(int row, int col) {
    uint32_t off = (uint32_t)row * 256u + (uint32_t)col * 2u;
    return off ^ (((uint32_t)row & 7u) << 4);
}
__device__ __forceinline__ void ldsm_x4(uint32_t* r, uint32_t addr) {
    asm volatile("ldmatrix.sync.aligned.m8n8.x4.shared.b16 {%0,%1,%2,%3}, [%4];"
                 : "=r"(r[0]), "=r"(r[1]), "=r"(r[2]), "=r"(r[3]) : "r"(addr));
}
__device__ __forceinline__ void mma_bf16(float* c, const uint32_t* a, const uint32_t* b) {
    asm volatile("mma.sync.aligned.m16n8k16.row.col.f32.bf16.bf16.f32 "
                 "{%0,%1,%2,%3}, {%4,%5,%6,%7}, {%8,%9}, {%0,%1,%2,%3};"
                 : "+f"(c[0]), "+f"(c[1]), "+f"(c[2]), "+f"(c[3])
                 : "r"(a[0]), "r"(a[1]), "r"(a[2]), "r"(a[3]), "r"(b[0]), "r"(b[1]));
}
// evict_last access-policy handle (per-thread, cheap)
__device__ __forceinline__ uint64_t mk_policy_el() {
    uint64_t pol;
    asm("createpolicy.fractional.L2::evict_last.b64 %0, 1.0;" : "=l"(pol));
    return pol;
}
// gather load with L2 cache-hint policy
__device__ __forceinline__ uint2 ldg_el(const void* p, uint64_t pol) {
    uint2 r;
    asm volatile("ld.global.nc.L2::cache_hint.v2.u32 {%0,%1}, [%2], %3;"
                 : "=r"(r.x), "=r"(r.y) : "l"(p), "l"(pol));
    return r;
}

// ---------------- CSR build ---------------------------------------------------
__global__ void k_init(const unsigned int* __restrict__ w) {
    int i = blockIdx.x * blockDim.x + threadIdx.x;
    if (i < NN) g_deg[i] = 0;
    if (i < 4096 && w[2 * i + 1] != 0u) g_flag = 1;
}
__device__ __forceinline__ int ld_edge(const void* ei, long long pos, int is64) {
    if (is64) return (int)((const long long*)ei)[pos];
    return ((const int*)ei)[pos];
}
__global__ void k_hist(const void* __restrict__ ei) {
    int e = blockIdx.x * blockDim.x + threadIdx.x;
    if (e >= EE) return;
    int is64 = (g_flag == 0);
    atomicAdd(&g_deg[ld_edge(ei, (long long)EE + e, is64)], 1);
}
__global__ void k_scan1() {
    __shared__ int sh[1024];
    int i = blockIdx.x * 1024 + threadIdx.x;
    int v = (i < NN) ? g_deg[i] : 0;
    sh[threadIdx.x] = v;
    __syncthreads();
    for (int d = 1; d < 1024; d <<= 1) {
        int t = (threadIdx.x >= d) ? sh[threadIdx.x - d] : 0;
        __syncthreads();
        sh[threadIdx.x] += t;
        __syncthreads();
    }
    if (i < NN) g_off[i] = sh[threadIdx.x] - v;
    if (threadIdx.x == 1023) g_bsum[blockIdx.x] = sh[1023];
}
__global__ void k_scan3() {
    __shared__ int sbase;
    if (threadIdx.x < 32) {
        int v = 0;
        for (int j = (int)threadIdx.x; j < (int)blockIdx.x; j += 32) v += g_bsum[j];
        for (int o = 16; o; o >>= 1) v += __shfl_xor_sync(0xFFFFFFFFu, v, o);
        if (threadIdx.x == 0) sbase = v;
    }
    __syncthreads();
    int i = blockIdx.x * 1024 + threadIdx.x;
    if (i >= NN) return;
    int o = g_off[i] + sbase;
    g_off[i] = o;
    g_cur[i] = o;
    int d = g_deg[i];
    g_dinv[i] = 1.0f / (float)(d > 1 ? d : 1);
}
__global__ void k_scatter(const void* __restrict__ ei) {
    int e = blockIdx.x * blockDim.x + threadIdx.x;
    if (e >= EE) return;
    int is64 = (g_flag == 0);
    int s = ld_edge(ei, (long long)e, is64);
    int d = ld_edge(ei, (long long)EE + e, is64);
    g_srcs[atomicAdd(&g_cur[d], 1)] = s;
}

// ---------------- weight prep -------------------------------------------------
__global__ void k_prep_w(const float* __restrict__ W1l, const float* __restrict__ W1r,
                         const float* __restrict__ W2l, const float* __restrict__ W2r,
                         const float* __restrict__ Wlin) {
    int i = blockIdx.x * blockDim.x + threadIdx.x;
    float v;
    unsigned char *hi, *lo;
    uint32_t off;
    if (i < 65536) {
        int layer = i >> 15, e = i & 32767;
        int n = e >> 7, k = e & 127;
        const float* Wl = layer ? W2l : W1l;
        const float* Wr = layer ? W2r : W1r;
        v = (n < 128) ? Wl[k * 128 + n] : Wr[k * 128 + (n - 128)];
        hi = layer ? g_w2hi : g_w1hi;
        lo = layer ? g_w2lo : g_w1lo;
        off = swz(n, k);
    } else if (i < 65536 + 8192) {
        int e = i - 65536;
        int n = e >> 7, k = e & 127;
        v = Wlin[k * 64 + n];
        hi = g_wfhi; lo = g_wflo;
        off = swz(n, k);
    } else return;
    __nv_bfloat16 h = __float2bfloat16_rn(v);
    __nv_bfloat16 l = __float2bfloat16_rn(v - __bfloat162float(h));
    *(__nv_bfloat16*)(hi + off) = h;
    *(__nv_bfloat16*)(lo + off) = l;
}

// ---------------- mma.sync GEMM ----------------------------------------------
// SPLIT: cols [0,128) -> UB fp16, cols [128,256) -> V fp16. Else fp32 C + bias.
template <int NC, bool SPLIT>
__global__ void __launch_bounds__(256, 1) k_gemm_mma(
    const float* __restrict__ A,
    const unsigned char* __restrict__ Bhi, const unsigned char* __restrict__ Blo,
    const float* __restrict__ bias,
    float* __restrict__ C, __half* __restrict__ UB, __half* __restrict__ V) {
    extern __shared__ unsigned char sm[];
    const int BIAS = 0;
    const int AHI = 1024;
    const int ALO = AHI + 32768;
    const int BHI = ALO + 32768;
    const int BLO = BHI + NC * 256;
    uint32_t sb = smem_u32(sm);
    int tid = threadIdx.x, wid = tid >> 5, lane = tid & 31;

    const int BW = NC * 256 / 16;
    for (int i = tid; i < BW; i += 256) {
        ((float4*)(sm + BHI))[i] = ((const float4*)Bhi)[i];
        ((float4*)(sm + BLO))[i] = ((const float4*)Blo)[i];
    }
    if (bias) for (int i = tid; i < NC; i += 256) ((float*)(sm + BIAS))[i] = bias[i];

    int row0 = blockIdx.x * 128;
    {
        int r = tid >> 1, half = tid & 1;
        int row = row0 + r;
        const float* ap = A + (size_t)row * 128 + half * 64;
        for (int cc = 0; cc < 64; cc += 4) {
            float4 v = (row < NN) ? *(const float4*)(ap + cc)
                                  : make_float4(0.f, 0.f, 0.f, 0.f);
            __nv_bfloat16 hx = __float2bfloat16_rn(v.x), hy = __float2bfloat16_rn(v.y);
            __nv_bfloat16 hz = __float2bfloat16_rn(v.z), hw = __float2bfloat16_rn(v.w);
            __nv_bfloat162 h0, h1, l0, l1;
            h0.x = hx; h0.y = hy; h1.x = hz; h1.y = hw;
            l0.x = __float2bfloat16_rn(v.x - __bfloat162float(hx));
            l0.y = __float2bfloat16_rn(v.y - __bfloat162float(hy));
            l1.x = __float2bfloat16_rn(v.z - __bfloat162float(hz));
            l1.y = __float2bfloat16_rn(v.w - __bfloat162float(hw));
            uint32_t so = swz(r, half * 64 + cc);
            *(__nv_bfloat162*)(sm + AHI + so)     = h0;
            *(__nv_bfloat162*)(sm + AHI + so + 4) = h1;
            *(__nv_bfloat162*)(sm + ALO + so)     = l0;
            *(__nv_bfloat162*)(sm + ALO + so + 4) = l1;
        }
    }
    __syncthreads();

    const int WARP_N = NC / 2;
    const int NPAIRS = WARP_N / 16;
    const int NB8    = WARP_N / 8;
    int warp_m = (wid & 3) * 32;
    int warp_n = (wid >> 2) * WARP_N;

    float c[2][NB8][4];
#pragma unroll
    for (int mb = 0; mb < 2; mb++)
#pragma unroll
        for (int nb = 0; nb < NB8; nb++)
#pragma unroll
            for (int j = 0; j < 4; j++) c[mb][nb][j] = 0.f;

    int a_r = ((lane >> 3) & 1) * 8 + (lane & 7);
    int a_c = (lane >> 4) * 8;
    int b_r = (lane >> 4) * 8 + (lane & 7);
    int b_c = ((lane >> 3) & 1) * 8;

#pragma unroll
    for (int pass = 0; pass < 3; pass++) {
        uint32_t abase = sb + (pass == 2 ? ALO : AHI);
        uint32_t bbase = sb + (pass == 1 ? BLO : BHI);
#pragma unroll
        for (int k = 0; k < 128; k += 16) {
            uint32_t afr[2][4];
#pragma unroll
            for (int mb = 0; mb < 2; mb++)
                ldsm_x4(afr[mb], abase + swz(warp_m + mb * 16 + a_r, k + a_c));
#pragma unroll
            for (int np = 0; np < NPAIRS; np++) {
                uint32_t bfr[4];
                ldsm_x4(bfr, bbase + swz(warp_n + np * 16 + b_r, k + b_c));
#pragma unroll
                for (int mb = 0; mb < 2; mb++) {
                    mma_bf16(c[mb][np * 2],     afr[mb], bfr);
                    mma_bf16(c[mb][np * 2 + 1], afr[mb], bfr + 2);
                }
            }
        }
    }

    int g = lane >> 2, tg = lane & 3;
    if (SPLIT) {
        bool is_u = (warp_n < 128);
        __half* base = is_u ? UB : V;
        int coff = is_u ? 0 : 128;
#pragma unroll
        for (int mb = 0; mb < 2; mb++) {
#pragma unroll
            for (int nb = 0; nb < NB8; nb++) {
                int col = warp_n + nb * 8 + tg * 2 - coff;
                int r1 = row0 + warp_m + mb * 16 + g;
                int r2 = r1 + 8;
                if (r1 < NN)
                    *(__half2*)(base + (size_t)r1 * 128 + col) =
                        __floats2half2_rn(c[mb][nb][0], c[mb][nb][1]);
                if (r2 < NN)
                    *(__half2*)(base + (size_t)r2 * 128 + col) =
                        __floats2half2_rn(c[mb][nb][2], c[mb][nb][3]);
            }
        }
    } else {
        const float* bs = (const float*)(sm + BIAS);
#pragma unroll
        for (int mb = 0; mb < 2; mb++) {
#pragma unroll
            for (int nb = 0; nb < NB8; nb++) {
                int col = warp_n + nb * 8 + tg * 2;
                float bx = bs[col], by = bs[col + 1];
                int r1 = row0 + warp_m + mb * 16 + g;
                if (r1 < NN)
                    *(float2*)(C + (size_t)r1 * NC + col) =
                        make_float2(c[mb][nb][0] + bx, c[mb][nb][1] + by);
                int r2 = r1 + 8;
                if (r2 < NN)
                    *(float2*)(C + (size_t)r2 * NC + col) =
                        make_float2(c[mb][nb][2] + bx, c[mb][nb][3] + by);
            }
        }
    }
}

// ---------------- aggregation: R5 loop + L2 policy hints ---------------------
// gathers: evict_last cache-hint (pin ub); v/res/out: streaming (evict-first).
__global__ void __launch_bounds__(256) k_agg(
    const __half* __restrict__ ub,
    const __half* __restrict__ v,
    const float* __restrict__ bias,
    const float* __restrict__ res,
    float* __restrict__ out) {
    int node = blockIdx.x * 8 + (threadIdx.x >> 5);
    if (node >= NN) return;
    int lane = threadIdx.x & 31;
    int off = g_off[node];
    int d = g_deg[node];

    uint64_t pol = mk_policy_el();
    float ax = 0.f, ay = 0.f, az = 0.f, aw = 0.f;
    const __half* uvb = ub + (size_t)lane * 4;

    int e = 0;
#pragma unroll 1
    for (; e + 4 <= d; e += 4) {
        int s0 = __ldg(&g_srcs[off + e]);
        int s1 = __ldg(&g_srcs[off + e + 1]);
        int s2 = __ldg(&g_srcs[off + e + 2]);
        int s3 = __ldg(&g_srcs[off + e + 3]);
        uint2 r0 = ldg_el(uvb + (size_t)s0 * 128, pol);
        uint2 r1 = ldg_el(uvb + (size_t)s1 * 128, pol);
        uint2 r2 = ldg_el(uvb + (size_t)s2 * 128, pol);
        uint2 r3 = ldg_el(uvb + (size_t)s3 * 128, pol);
        float2 a0 = __half22float2(*(__half2*)&r0.x), b0 = __half22float2(*(__half2*)&r0.y);
        float2 a1 = __half22float2(*(__half2*)&r1.x), b1 = __half22float2(*(__half2*)&r1.y);
        float2 a2 = __half22float2(*(__half2*)&r2.x), b2 = __half22float2(*(__half2*)&r2.y);
        float2 a3 = __half22float2(*(__half2*)&r3.x), b3 = __half22float2(*(__half2*)&r3.y);
        ax += a0.x + a1.x + a2.x + a3.x;
        ay += a0.y + a1.y + a2.y + a3.y;
        az += b0.x + b1.x + b2.x + b3.x;
        aw += b0.y + b1.y + b2.y + b3.y;
    }
    for (; e < d; e++) {
        int s = __ldg(&g_srcs[off + e]);
        uint2 r = ldg_el(uvb + (size_t)s * 128, pol);
        float2 a = __half22float2(*(__half2*)&r.x), b = __half22float2(*(__half2*)&r.y);
        ax += a.x; ay += a.y; az += b.x; aw += b.y;
    }

    float di = g_dinv[node];
    uint2 vr = __ldcs((const uint2*)(v + (size_t)node * 128 + lane * 4));
    float2 v0 = __half22float2(*(__half2*)&vr.x), v1 = __half22float2(*(__half2*)&vr.y);
    float4 b = *(const float4*)(bias + lane * 4);
    float rx = fmaf(ax, di, v0.x + b.x);
    float ry = fmaf(ay, di, v0.y + b.y);
    float rz = fmaf(az, di, v1.x + b.z);
    float rw = fmaf(aw, di, v1.y + b.w);
    if (res) {
        float4 h = __ldcs((const float4*)(res + (size_t)node * 128 + lane * 4));
        rx += h.x; ry += h.y; rz += h.z; rw += h.w;
    }
    rx = fmaxf(rx, 0.f); ry = fmaxf(ry, 0.f);
    rz = fmaxf(rz, 0.f); rw = fmaxf(rw, 0.f);
    __stcs((float4*)(out + (size_t)node * 128 + lane * 4), make_float4(rx, ry, rz, rw));
}

// ---------------- launch ------------------------------------------------------
extern "C" void kernel_launch(void* const* d_in, const int* in_sizes, int n_in,
                              void* d_out, int out_size) {
    const float* x    = (const float*)d_in[0];
    const void*  ei   = d_in[1];
    const float* W1l  = (const float*)d_in[2];
    const float* b1   = (const float*)d_in[3];
    const float* W1r  = (const float*)d_in[4];
    const float* W2l  = (const float*)d_in[5];
    const float* b2   = (const float*)d_in[6];
    const float* W2r  = (const float*)d_in[7];
    const float* Wlin = (const float*)d_in[8];
    const float* blin = (const float*)d_in[9];
    float* out = (float*)d_out;

    const size_t SM_DUAL  = 1024 + 2 * 32768 + 2 * 256 * 256;
    const size_t SM_FINAL = 1024 + 2 * 32768 + 2 * 64 * 256;
    cudaFuncSetAttribute(k_gemm_mma<256, true>, cudaFuncAttributeMaxDynamicSharedMemorySize, (int)SM_DUAL);
    cudaFuncSetAttribute(k_gemm_mma<64, false>, cudaFuncAttributeMaxDynamicSharedMemorySize, (int)SM_FINAL);

    void *p_ub, *p_v, *p_h1, *p_h, *p_w1h, *p_w1l, *p_w2h, *p_w2l, *p_wfh, *p_wfl;
    cudaGetSymbolAddress(&p_ub, g_ub);
    cudaGetSymbolAddress(&p_v,  g_v);
    cudaGetSymbolAddress(&p_h1, g_h1);
    cudaGetSymbolAddress(&p_h,  g_h);
    cudaGetSymbolAddress(&p_w1h, g_w1hi);
    cudaGetSymbolAddress(&p_w1l, g_w1lo);
    cudaGetSymbolAddress(&p_w2h, g_w2hi);
    cudaGetSymbolAddress(&p_w2l, g_w2lo);
    cudaGetSymbolAddress(&p_wfh, g_wfhi);
    cudaGetSymbolAddress(&p_wfl, g_wflo);
    __half* ub = (__half*)p_ub;
    __half* vv = (__half*)p_v;
    float*  h1 = (float*)p_h1;
    float*  h  = (float*)p_h;

    const int NB_N   = (NN + 255) / 256;
    const int NB_E   = (EE + 255) / 256;
    const int NB_SC  = (NN + 1023) / 1024;
    const int NB_TC  = (NN + 127) / 128;
    const int NB_AGG = (NN + 7) / 8;

    k_init<<<NB_N, 256>>>((const unsigned int*)ei);
    k_prep_w<<<(73728 + 255) / 256, 256>>>(W1l, W1r, W2l, W2r, Wlin);
    k_hist<<<NB_E, 256>>>(ei);
    k_scan1<<<NB_SC, 1024>>>();
    k_scan3<<<NB_SC, 1024>>>();
    k_scatter<<<NB_E, 256>>>(ei);

    k_gemm_mma<256, true><<<NB_TC, 256, SM_DUAL>>>(x, (unsigned char*)p_w1h, (unsigned char*)p_w1l, nullptr, nullptr, ub, vv);
    k_agg<<<NB_AGG, 256>>>(ub, vv, b1, nullptr, h1);
    k_gemm_mma<256, true><<<NB_TC, 256, SM_DUAL>>>(h1, (unsigned char*)p_w2h, (unsigned char*)p_w2l, nullptr, nullptr, ub, vv);
    k_agg<<<NB_AGG, 256>>>(ub, vv, b2, h1, h);
    k_gemm_mma<64, false><<<NB_TC, 256, SM_FINAL>>>(h, (unsigned char*)p_wfh, (unsigned char*)p_wfl, blin, out, nullptr, nullptr);
}

// round 17
// speedup vs baseline: 1.4861x; 1.0563x over previous
#include <cuda_runtime.h>
#include <cuda_bf16.h>
#include <cuda_fp16.h>
#include <cstdint>

#define NN 100000
#define EE 1600000

// ---------------- scratch (device globals) -----------------------------------
__device__ int   g_deg[NN];
__device__ int   g_off[NN];
__device__ int   g_cur[NN];
__device__ float g_dinv[NN];
__device__ int   g_srcs[EE];
__device__ int   g_bsum[128];
__device__ int   g_flag;
__device__ __align__(16) __half g_ub[(size_t)NN * 128];   // u = A@Wl, fp16 (gather target)
__device__ __align__(16) __half g_v [(size_t)NN * 128];   // v = A@Wr, fp16 (streamed)
__device__ __align__(16) __half g_h1[(size_t)NN * 128];   // layer-1 out, fp16
__device__ __align__(16) __half g_h [(size_t)NN * 128];   // layer-2 out, fp16
__device__ __align__(16) unsigned char g_w1hi[256 * 256];
__device__ __align__(16) unsigned char g_w1lo[256 * 256];
__device__ __align__(16) unsigned char g_w2hi[256 * 256];
__device__ __align__(16) unsigned char g_w2lo[256 * 256];
__device__ __align__(16) unsigned char g_wfhi[64 * 256];
__device__ __align__(16) unsigned char g_wflo[64 * 256];

// ---------------- helpers -----------------------------------------------------
__device__ __forceinline__ uint32_t smem_u32(const void* p) {
    uint32_t a;
    asm("{ .reg .u64 t; cvta.to.shared.u64 t, %1; cvt.u32.u64 %0, t; }" : "=r"(a) : "l"(p));
    return a;
}
__device__ __forceinline__ uint32_t swz(int row, int col) {
    uint32_t off = (uint32_t)row * 256u + (uint32_t)col * 2u;
    return off ^ (((uint32_t)row & 7u) << 4);
}
__device__ __forceinline__ void ldsm_x4(uint32_t* r, uint32_t addr) {
    asm volatile("ldmatrix.sync.aligned.m8n8.x4.shared.b16 {%0,%1,%2,%3}, [%4];"
                 : "=r"(r[0]), "=r"(r[1]), "=r"(r[2]), "=r"(r[3]) : "r"(addr));
}
__device__ __forceinline__ void mma_bf16(float* c, const uint32_t* a, const uint32_t* b) {
    asm volatile("mma.sync.aligned.m16n8k16.row.col.f32.bf16.bf16.f32 "
                 "{%0,%1,%2,%3}, {%4,%5,%6,%7}, {%8,%9}, {%0,%1,%2,%3};"
                 : "+f"(c[0]), "+f"(c[1]), "+f"(c[2]), "+f"(c[3])
                 : "r"(a[0]), "r"(a[1]), "r"(a[2]), "r"(a[3]), "r"(b[0]), "r"(b[1]));
}
__device__ __forceinline__ uint64_t mk_policy_el() {
    uint64_t pol;
    asm("createpolicy.fractional.L2::evict_last.b64 %0, 1.0;" : "=l"(pol));
    return pol;
}
__device__ __forceinline__ uint2 ldg_el(const void* p, uint64_t pol) {
    uint2 r;
    asm volatile("ld.global.nc.L2::cache_hint.v2.u32 {%0,%1}, [%2], %3;"
                 : "=r"(r.x), "=r"(r.y) : "l"(p), "l"(pol));
    return r;
}
// split float -> bf16 hi/lo pair packed as (hi0,hi1),(lo0,lo1)
__device__ __forceinline__ void split2(float x, float y, uint32_t& hi, uint32_t& lo) {
    __nv_bfloat162 h, l;
    h.x = __float2bfloat16_rn(x);
    h.y = __float2bfloat16_rn(y);
    l.x = __float2bfloat16_rn(x - __bfloat162float(h.x));
    l.y = __float2bfloat16_rn(y - __bfloat162float(h.y));
    hi = *(uint32_t*)&h;
    lo = *(uint32_t*)&l;
}

// ---------------- CSR build ---------------------------------------------------
__global__ void k_init(const unsigned int* __restrict__ w) {
    int i = blockIdx.x * blockDim.x + threadIdx.x;
    if (i < NN) g_deg[i] = 0;
    if (i < 4096 && w[2 * i + 1] != 0u) g_flag = 1;
}
__device__ __forceinline__ int ld_edge(const void* ei, long long pos, int is64) {
    if (is64) return (int)((const long long*)ei)[pos];
    return ((const int*)ei)[pos];
}
__global__ void k_hist(const void* __restrict__ ei) {
    int e = blockIdx.x * blockDim.x + threadIdx.x;
    if (e >= EE) return;
    int is64 = (g_flag == 0);
    atomicAdd(&g_deg[ld_edge(ei, (long long)EE + e, is64)], 1);
}
__global__ void k_scan1() {
    __shared__ int sh[1024];
    int i = blockIdx.x * 1024 + threadIdx.x;
    int v = (i < NN) ? g_deg[i] : 0;
    sh[threadIdx.x] = v;
    __syncthreads();
    for (int d = 1; d < 1024; d <<= 1) {
        int t = (threadIdx.x >= d) ? sh[threadIdx.x - d] : 0;
        __syncthreads();
        sh[threadIdx.x] += t;
        __syncthreads();
    }
    if (i < NN) g_off[i] = sh[threadIdx.x] - v;
    if (threadIdx.x == 1023) g_bsum[blockIdx.x] = sh[1023];
}
__global__ void k_scan3() {
    __shared__ int sbase;
    if (threadIdx.x < 32) {
        int v = 0;
        for (int j = (int)threadIdx.x; j < (int)blockIdx.x; j += 32) v += g_bsum[j];
        for (int o = 16; o; o >>= 1) v += __shfl_xor_sync(0xFFFFFFFFu, v, o);
        if (threadIdx.x == 0) sbase = v;
    }
    __syncthreads();
    int i = blockIdx.x * 1024 + threadIdx.x;
    if (i >= NN) return;
    int o = g_off[i] + sbase;
    g_off[i] = o;
    g_cur[i] = o;
    int d = g_deg[i];
    g_dinv[i] = 1.0f / (float)(d > 1 ? d : 1);
}
__global__ void k_scatter(const void* __restrict__ ei) {
    int e = blockIdx.x * blockDim.x + threadIdx.x;
    if (e >= EE) return;
    int is64 = (g_flag == 0);
    int s = ld_edge(ei, (long long)e, is64);
    int d = ld_edge(ei, (long long)EE + e, is64);
    g_srcs[atomicAdd(&g_cur[d], 1)] = s;
}

// ---------------- weight prep -------------------------------------------------
__global__ void k_prep_w(const float* __restrict__ W1l, const float* __restrict__ W1r,
                         const float* __restrict__ W2l, const float* __restrict__ W2r,
                         const float* __restrict__ Wlin) {
    int i = blockIdx.x * blockDim.x + threadIdx.x;
    float v;
    unsigned char *hi, *lo;
    uint32_t off;
    if (i < 65536) {
        int layer = i >> 15, e = i & 32767;
        int n = e >> 7, k = e & 127;
        const float* Wl = layer ? W2l : W1l;
        const float* Wr = layer ? W2r : W1r;
        v = (n < 128) ? Wl[k * 128 + n] : Wr[k * 128 + (n - 128)];
        hi = layer ? g_w2hi : g_w1hi;
        lo = layer ? g_w2lo : g_w1lo;
        off = swz(n, k);
    } else if (i < 65536 + 8192) {
        int e = i - 65536;
        int n = e >> 7, k = e & 127;
        v = Wlin[k * 64 + n];
        hi = g_wfhi; lo = g_wflo;
        off = swz(n, k);
    } else return;
    __nv_bfloat16 h = __float2bfloat16_rn(v);
    __nv_bfloat16 l = __float2bfloat16_rn(v - __bfloat162float(h));
    *(__nv_bfloat16*)(hi + off) = h;
    *(__nv_bfloat16*)(lo + off) = l;
}

// ---------------- mma.sync GEMM ----------------------------------------------
// TA = float (layer 1: x) or __half (layer 2 / head: fp16 activations; exact split).
// SPLIT: cols [0,128) -> UB fp16, cols [128,256) -> V fp16. Else fp32 C + bias.
template <int NC, bool SPLIT, typename TA>
__global__ void __launch_bounds__(256, 1) k_gemm_mma(
    const TA* __restrict__ A,
    const unsigned char* __restrict__ Bhi, const unsigned char* __restrict__ Blo,
    const float* __restrict__ bias,
    float* __restrict__ C, __half* __restrict__ UB, __half* __restrict__ V) {
    extern __shared__ unsigned char sm[];
    const int BIAS = 0;
    const int AHI = 1024;
    const int ALO = AHI + 32768;
    const int BHI = ALO + 32768;
    const int BLO = BHI + NC * 256;
    uint32_t sb = smem_u32(sm);
    int tid = threadIdx.x, wid = tid >> 5, lane = tid & 31;

    const int BW = NC * 256 / 16;
    for (int i = tid; i < BW; i += 256) {
        ((float4*)(sm + BHI))[i] = ((const float4*)Bhi)[i];
        ((float4*)(sm + BLO))[i] = ((const float4*)Blo)[i];
    }
    if (bias) for (int i = tid; i < NC; i += 256) ((float*)(sm + BIAS))[i] = bias[i];

    int row0 = blockIdx.x * 128;
    {
        int r = tid >> 1, hh = tid & 1;
        int row = row0 + r;
        if (sizeof(TA) == 4) {
            const float* ap = (const float*)A + (size_t)row * 128 + hh * 64;
            for (int cc = 0; cc < 64; cc += 8) {
                float4 va = (row < NN) ? *(const float4*)(ap + cc)
                                       : make_float4(0.f, 0.f, 0.f, 0.f);
                float4 vb = (row < NN) ? *(const float4*)(ap + cc + 4)
                                       : make_float4(0.f, 0.f, 0.f, 0.f);
                uint4 hi4, lo4;
                split2(va.x, va.y, hi4.x, lo4.x);
                split2(va.z, va.w, hi4.y, lo4.y);
                split2(vb.x, vb.y, hi4.z, lo4.z);
                split2(vb.z, vb.w, hi4.w, lo4.w);
                uint32_t so = swz(r, hh * 64 + cc);
                *(uint4*)(sm + AHI + so) = hi4;
                *(uint4*)(sm + ALO + so) = lo4;
            }
        } else {
            const __half* ap = (const __half*)A + (size_t)row * 128 + hh * 64;
            for (int cc = 0; cc < 64; cc += 8) {
                uint4 raw = (row < NN) ? *(const uint4*)(ap + cc)
                                       : make_uint4(0u, 0u, 0u, 0u);
                uint4 hi4, lo4;
                const uint32_t* rw = (const uint32_t*)&raw;
                uint32_t* hp = (uint32_t*)&hi4;
                uint32_t* lp = (uint32_t*)&lo4;
#pragma unroll
                for (int j = 0; j < 4; j++) {
                    float2 f = __half22float2(*(__half2*)&rw[j]);
                    split2(f.x, f.y, hp[j], lp[j]);   // exact for fp16 inputs
                }
                uint32_t so = swz(r, hh * 64 + cc);
                *(uint4*)(sm + AHI + so) = hi4;
                *(uint4*)(sm + ALO + so) = lo4;
            }
        }
    }
    __syncthreads();

    const int WARP_N = NC / 2;
    const int NPAIRS = WARP_N / 16;
    const int NB8    = WARP_N / 8;
    int warp_m = (wid & 3) * 32;
    int warp_n = (wid >> 2) * WARP_N;

    float c[2][NB8][4];
#pragma unroll
    for (int mb = 0; mb < 2; mb++)
#pragma unroll
        for (int nb = 0; nb < NB8; nb++)
#pragma unroll
            for (int j = 0; j < 4; j++) c[mb][nb][j] = 0.f;

    int a_r = ((lane >> 3) & 1) * 8 + (lane & 7);
    int a_c = (lane >> 4) * 8;
    int b_r = (lane >> 4) * 8 + (lane & 7);
    int b_c = ((lane >> 3) & 1) * 8;

#pragma unroll
    for (int pass = 0; pass < 3; pass++) {
        uint32_t abase = sb + (pass == 2 ? ALO : AHI);
        uint32_t bbase = sb + (pass == 1 ? BLO : BHI);
#pragma unroll
        for (int k = 0; k < 128; k += 16) {
            uint32_t afr[2][4];
#pragma unroll
            for (int mb = 0; mb < 2; mb++)
                ldsm_x4(afr[mb], abase + swz(warp_m + mb * 16 + a_r, k + a_c));
#pragma unroll
            for (int np = 0; np < NPAIRS; np++) {
                uint32_t bfr[4];
                ldsm_x4(bfr, bbase + swz(warp_n + np * 16 + b_r, k + b_c));
#pragma unroll
                for (int mb = 0; mb < 2; mb++) {
                    mma_bf16(c[mb][np * 2],     afr[mb], bfr);
                    mma_bf16(c[mb][np * 2 + 1], afr[mb], bfr + 2);
                }
            }
        }
    }

    int g = lane >> 2, tg = lane & 3;
    if (SPLIT) {
        bool is_u = (warp_n < 128);
        __half* base = is_u ? UB : V;
        int coff = is_u ? 0 : 128;
#pragma unroll
        for (int mb = 0; mb < 2; mb++) {
#pragma unroll
            for (int nb = 0; nb < NB8; nb++) {
                int col = warp_n + nb * 8 + tg * 2 - coff;
                int r1 = row0 + warp_m + mb * 16 + g;
                int r2 = r1 + 8;
                if (r1 < NN)
                    *(__half2*)(base + (size_t)r1 * 128 + col) =
                        __floats2half2_rn(c[mb][nb][0], c[mb][nb][1]);
                if (r2 < NN)
                    *(__half2*)(base + (size_t)r2 * 128 + col) =
                        __floats2half2_rn(c[mb][nb][2], c[mb][nb][3]);
            }
        }
    } else {
        const float* bs = (const float*)(sm + BIAS);
#pragma unroll
        for (int mb = 0; mb < 2; mb++) {
#pragma unroll
            for (int nb = 0; nb < NB8; nb++) {
                int col = warp_n + nb * 8 + tg * 2;
                float bx = bs[col], by = bs[col + 1];
                int r1 = row0 + warp_m + mb * 16 + g;
                if (r1 < NN)
                    *(float2*)(C + (size_t)r1 * NC + col) =
                        make_float2(c[mb][nb][0] + bx, c[mb][nb][1] + by);
                int r2 = r1 + 8;
                if (r2 < NN)
                    *(float2*)(C + (size_t)r2 * NC + col) =
                        make_float2(c[mb][nb][2] + bx, c[mb][nb][3] + by);
            }
        }
    }
}

// ---------------- aggregation: fp16 in/out, fp32 accumulate ------------------
__global__ void __launch_bounds__(256) k_agg(
    const __half* __restrict__ ub,
    const __half* __restrict__ v,
    const float* __restrict__ bias,
    const __half* __restrict__ res,     // fp16 residual (may be null)
    __half* __restrict__ out) {         // fp16 output
    int node = blockIdx.x * 8 + (threadIdx.x >> 5);
    if (node >= NN) return;
    int lane = threadIdx.x & 31;
    int off = g_off[node];
    int d = g_deg[node];

    uint64_t pol = mk_policy_el();
    float ax = 0.f, ay = 0.f, az = 0.f, aw = 0.f;
    const __half* uvb = ub + (size_t)lane * 4;

    int e = 0;
#pragma unroll 1
    for (; e + 4 <= d; e += 4) {
        int s0 = __ldg(&g_srcs[off + e]);
        int s1 = __ldg(&g_srcs[off + e + 1]);
        int s2 = __ldg(&g_srcs[off + e + 2]);
        int s3 = __ldg(&g_srcs[off + e + 3]);
        uint2 r0 = ldg_el(uvb + (size_t)s0 * 128, pol);
        uint2 r1 = ldg_el(uvb + (size_t)s1 * 128, pol);
        uint2 r2 = ldg_el(uvb + (size_t)s2 * 128, pol);
        uint2 r3 = ldg_el(uvb + (size_t)s3 * 128, pol);
        float2 a0 = __half22float2(*(__half2*)&r0.x), b0 = __half22float2(*(__half2*)&r0.y);
        float2 a1 = __half22float2(*(__half2*)&r1.x), b1 = __half22float2(*(__half2*)&r1.y);
        float2 a2 = __half22float2(*(__half2*)&r2.x), b2 = __half22float2(*(__half2*)&r2.y);
        float2 a3 = __half22float2(*(__half2*)&r3.x), b3 = __half22float2(*(__half2*)&r3.y);
        ax += a0.x + a1.x + a2.x + a3.x;
        ay += a0.y + a1.y + a2.y + a3.y;
        az += b0.x + b1.x + b2.x + b3.x;
        aw += b0.y + b1.y + b2.y + b3.y;
    }
    for (; e < d; e++) {
        int s = __ldg(&g_srcs[off + e]);
        uint2 r = ldg_el(uvb + (size_t)s * 128, pol);
        float2 a = __half22float2(*(__half2*)&r.x), b = __half22float2(*(__half2*)&r.y);
        ax += a.x; ay += a.y; az += b.x; aw += b.y;
    }

    float di = g_dinv[node];
    uint2 vr = __ldcs((const uint2*)(v + (size_t)node * 128 + lane * 4));
    float2 v0 = __half22float2(*(__half2*)&vr.x), v1 = __half22float2(*(__half2*)&vr.y);
    float4 b = *(const float4*)(bias + lane * 4);
    float rx = fmaf(ax, di, v0.x + b.x);
    float ry = fmaf(ay, di, v0.y + b.y);
    float rz = fmaf(az, di, v1.x + b.z);
    float rw = fmaf(aw, di, v1.y + b.w);
    if (res) {
        uint2 hr = __ldcs((const uint2*)(res + (size_t)node * 128 + lane * 4));
        float2 h0 = __half22float2(*(__half2*)&hr.x), h1 = __half22float2(*(__half2*)&hr.y);
        rx += h0.x; ry += h0.y; rz += h1.x; rw += h1.y;
    }
    rx = fmaxf(rx, 0.f); ry = fmaxf(ry, 0.f);
    rz = fmaxf(rz, 0.f); rw = fmaxf(rw, 0.f);
    uint2 o;
    *(__half2*)&o.x = __floats2half2_rn(rx, ry);
    *(__half2*)&o.y = __floats2half2_rn(rz, rw);
    __stcs((uint2*)(out + (size_t)node * 128 + lane * 4), o);
}

// ---------------- launch ------------------------------------------------------
extern "C" void kernel_launch(void* const* d_in, const int* in_sizes, int n_in,
                              void* d_out, int out_size) {
    const float* x    = (const float*)d_in[0];
    const void*  ei   = d_in[1];
    const float* W1l  = (const float*)d_in[2];
    const float* b1   = (const float*)d_in[3];
    const float* W1r  = (const float*)d_in[4];
    const float* W2l  = (const float*)d_in[5];
    const float* b2   = (const float*)d_in[6];
    const float* W2r  = (const float*)d_in[7];
    const float* Wlin = (const float*)d_in[8];
    const float* blin = (const float*)d_in[9];
    float* out = (float*)d_out;

    const size_t SM_DUAL  = 1024 + 2 * 32768 + 2 * 256 * 256;
    const size_t SM_FINAL = 1024 + 2 * 32768 + 2 * 64 * 256;
    cudaFuncSetAttribute(k_gemm_mma<256, true, float>,   cudaFuncAttributeMaxDynamicSharedMemorySize, (int)SM_DUAL);
    cudaFuncSetAttribute(k_gemm_mma<256, true, __half>,  cudaFuncAttributeMaxDynamicSharedMemorySize, (int)SM_DUAL);
    cudaFuncSetAttribute(k_gemm_mma<64, false, __half>,  cudaFuncAttributeMaxDynamicSharedMemorySize, (int)SM_FINAL);

    void *p_ub, *p_v, *p_h1, *p_h, *p_w1h, *p_w1l, *p_w2h, *p_w2l, *p_wfh, *p_wfl;
    cudaGetSymbolAddress(&p_ub, g_ub);
    cudaGetSymbolAddress(&p_v,  g_v);
    cudaGetSymbolAddress(&p_h1, g_h1);
    cudaGetSymbolAddress(&p_h,  g_h);
    cudaGetSymbolAddress(&p_w1h, g_w1hi);
    cudaGetSymbolAddress(&p_w1l, g_w1lo);
    cudaGetSymbolAddress(&p_w2h, g_w2hi);
    cudaGetSymbolAddress(&p_w2l, g_w2lo);
    cudaGetSymbolAddress(&p_wfh, g_wfhi);
    cudaGetSymbolAddress(&p_wfl, g_wflo);
    __half* ub = (__half*)p_ub;
    __half* vv = (__half*)p_v;
    __half* h1 = (__half*)p_h1;
    __half* h  = (__half*)p_h;

    const int NB_N   = (NN + 255) / 256;
    const int NB_E   = (EE + 255) / 256;
    const int NB_SC  = (NN + 1023) / 1024;
    const int NB_TC  = (NN + 127) / 128;
    const int NB_AGG = (NN + 7) / 8;

    k_init<<<NB_N, 256>>>((const unsigned int*)ei);
    k_prep_w<<<(73728 + 255) / 256, 256>>>(W1l, W1r, W2l, W2r, Wlin);
    k_hist<<<NB_E, 256>>>(ei);
    k_scan1<<<NB_SC, 1024>>>();
    k_scan3<<<NB_SC, 1024>>>();
    k_scatter<<<NB_E, 256>>>(ei);

    k_gemm_mma<256, true, float><<<NB_TC, 256, SM_DUAL>>>(x, (unsigned char*)p_w1h, (unsigned char*)p_w1l, nullptr, nullptr, ub, vv);
    k_agg<<<NB_AGG, 256>>>(ub, vv, b1, nullptr, h1);
    k_gemm_mma<256, true, __half><<<NB_TC, 256, SM_DUAL>>>(h1, (unsigned char*)p_w2h, (unsigned char*)p_w2l, nullptr, nullptr, ub, vv);
    k_agg<<<NB_AGG, 256>>>(ub, vv, b2, h1, h);
    k_gemm_mma<64, false, __half><<<NB_TC, 256, SM_FINAL>>>(h, (unsigned char*)p_wfh, (unsigned char*)p_wfl, blin, out, nullptr, nullptr);
}